// round 9
// baseline (speedup 1.0000x reference)
#include <cuda_runtime.h>
#include <cuda_bf16.h>
#include <math.h>
#include <stdint.h>

#define B_ 64
#define T_ 512
#define D_ 512
#define U_ 1024
#define G_ 4096   // 4*U

// ---------------------------------------------------------------------------
// Scratch (__device__ globals: allocation-free rule)
// ---------------------------------------------------------------------------
__device__ float         g_xz[(size_t)B_ * T_ * G_];     // fp32 input projections
__device__ __nv_bfloat16 g_xhi[(size_t)B_ * T_ * D_];    // x split
__device__ __nv_bfloat16 g_xlo[(size_t)B_ * T_ * D_];
__device__ __nv_bfloat16 g_Wt_hi[(size_t)G_ * D_];       // W^T split  [4096][512]
__device__ __nv_bfloat16 g_Wt_lo[(size_t)G_ * D_];
__device__ __nv_bfloat16 g_Rt_hi[(size_t)G_ * U_];       // R^T split  [4096][1024]
__device__ __nv_bfloat16 g_Rt_lo[(size_t)G_ * U_];
__device__ __nv_bfloat16 g_hhi[2][B_ * U_];              // h ping-pong, split
__device__ __nv_bfloat16 g_hlo[2][B_ * U_];
__device__ int           g_flags[T_ * 128];              // grid-barrier flags

// ---------------------------------------------------------------------------
// Helpers
// ---------------------------------------------------------------------------
__device__ __forceinline__ uint32_t smem_u32(const void* p) {
    uint32_t a;
    asm("{ .reg .u64 t; cvta.to.shared.u64 t, %1; cvt.u32.u64 %0, t; }" : "=r"(a) : "l"(p));
    return a;
}
__device__ __forceinline__ uint32_t sw128(uint32_t off) { return off ^ ((off >> 3) & 0x70); }
__device__ __forceinline__ uint32_t sw64 (uint32_t off) { return off ^ ((off >> 3) & 0x30); }

#define CP16(dst, src) \
    asm volatile("cp.async.cg.shared.global [%0], [%1], 16;" :: "r"(dst), "l"(src))
#define CP_COMMIT() asm volatile("cp.async.commit_group;" ::: "memory")
#define CP_WAIT1()  asm volatile("cp.async.wait_group 1;" ::: "memory")
#define CP_WAIT0()  asm volatile("cp.async.wait_group 0;" ::: "memory")

__device__ __forceinline__ void ldsm_x4(uint32_t* r, uint32_t addr) {
    asm volatile("ldmatrix.sync.aligned.m8n8.x4.shared.b16 {%0,%1,%2,%3}, [%4];"
                 : "=r"(r[0]), "=r"(r[1]), "=r"(r[2]), "=r"(r[3]) : "r"(addr));
}
__device__ __forceinline__ void ldsm_x2(uint32_t* r, uint32_t addr) {
    asm volatile("ldmatrix.sync.aligned.m8n8.x2.shared.b16 {%0,%1}, [%2];"
                 : "=r"(r[0]), "=r"(r[1]) : "r"(addr));
}
__device__ __forceinline__ void mma16816(float* c, const uint32_t* a, const uint32_t* b) {
    asm volatile(
        "mma.sync.aligned.m16n8k16.row.col.f32.bf16.bf16.f32 "
        "{%0,%1,%2,%3}, {%4,%5,%6,%7}, {%8,%9}, {%0,%1,%2,%3};"
        : "+f"(c[0]), "+f"(c[1]), "+f"(c[2]), "+f"(c[3])
        : "r"(a[0]), "r"(a[1]), "r"(a[2]), "r"(a[3]), "r"(b[0]), "r"(b[1]));
}

// ---------------------------------------------------------------------------
// Prep kernels
// ---------------------------------------------------------------------------
__global__ void init_state()
{
    int i = blockIdx.x * blockDim.x + threadIdx.x;
    if (i < B_ * U_) {
        __nv_bfloat16 z = __float2bfloat16(0.0f);
        g_hhi[0][i] = z; g_hlo[0][i] = z;
        g_hhi[1][i] = z; g_hlo[1][i] = z;
    }
    if (i < T_ * 128) g_flags[i] = 0;
}

__global__ void split_x(const float* __restrict__ x)
{
    size_t i = (size_t)blockIdx.x * blockDim.x + threadIdx.x;
    size_t n4 = (size_t)B_ * T_ * D_ / 4;
    if (i >= n4) return;
    float4 v = ((const float4*)x)[i];
    float vv[4] = {v.x, v.y, v.z, v.w};
    __nv_bfloat162* ph = (__nv_bfloat162*)g_xhi;
    __nv_bfloat162* pl = (__nv_bfloat162*)g_xlo;
    __nv_bfloat16 h[4], l[4];
    #pragma unroll
    for (int j = 0; j < 4; j++) {
        h[j] = __float2bfloat16(vv[j]);
        l[j] = __float2bfloat16(vv[j] - __bfloat162float(h[j]));
    }
    ph[2*i]     = __halves2bfloat162(h[0], h[1]);
    ph[2*i + 1] = __halves2bfloat162(h[2], h[3]);
    pl[2*i]     = __halves2bfloat162(l[0], l[1]);
    pl[2*i + 1] = __halves2bfloat162(l[2], l[3]);
}

// src [rows][cols] fp32 -> Wt/Rt [cols][rows] bf16 hi/lo (device-resolved dst)
__global__ void transpose_split_sel(const float* __restrict__ src,
                                    int which, int rows, int cols)
{
    __nv_bfloat16* dhi = which ? g_Rt_hi : g_Wt_hi;
    __nv_bfloat16* dlo = which ? g_Rt_lo : g_Wt_lo;
    __shared__ float t[32][33];
    int x = blockIdx.x * 32 + threadIdx.x;
    int y0 = blockIdx.y * 32;
    #pragma unroll
    for (int i = 0; i < 32; i += 8)
        t[threadIdx.y + i][threadIdx.x] = src[(size_t)(y0 + threadIdx.y + i) * cols + x];
    __syncthreads();
    int ox = y0 + threadIdx.x;
    #pragma unroll
    for (int i = 0; i < 32; i += 8) {
        int orow = blockIdx.x * 32 + threadIdx.y + i;
        float v = t[threadIdx.x][threadIdx.y + i];
        __nv_bfloat16 h = __float2bfloat16(v);
        dhi[(size_t)orow * rows + ox] = h;
        dlo[(size_t)orow * rows + ox] = __float2bfloat16(v - __bfloat162float(h));
    }
}

// ---------------------------------------------------------------------------
// xz = x @ W + bias via mma.sync (3-term bf16 split) — unchanged from R7
// ---------------------------------------------------------------------------
#define XAHI 0
#define XALO 8192
#define XBHI 16384
#define XBLO 24576
#define XSTG 32768

__global__ __launch_bounds__(256) void gemm_xz_mma(const float* __restrict__ bias)
{
    extern __shared__ __align__(1024) char sm[];
    uint32_t smb = smem_u32(sm);
    const int tid  = threadIdx.x;
    const int wid  = tid >> 5;
    const int lane = tid & 31;
    const int m0 = blockIdx.y * 128;
    const int n0 = blockIdx.x * 128;

    const char* xh = (const char*)g_xhi;
    const char* xl = (const char*)g_xlo;
    const char* wh = (const char*)g_Wt_hi;
    const char* wl = (const char*)g_Wt_lo;

    float acc[2][8][4] = {};

    auto issue = [&](int kc, int s) {
        uint32_t st = smb + s * XSTG;
        #pragma unroll
        for (int i = 0; i < 2; i++) {
            int idx = tid + 256 * i;
            int r = idx >> 2, g = idx & 3;
            CP16(st + XAHI + sw64(r * 64 + g * 16),
                 xh + (size_t)(m0 + r) * 1024 + kc * 64 + g * 16);
        }
        #pragma unroll
        for (int i = 0; i < 2; i++) {
            int idx = tid + 256 * i;
            int r = idx >> 2, g = idx & 3;
            CP16(st + XALO + sw64(r * 64 + g * 16),
                 xl + (size_t)(m0 + r) * 1024 + kc * 64 + g * 16);
        }
        #pragma unroll
        for (int i = 0; i < 2; i++) {
            int idx = tid + 256 * i;
            int r = idx >> 2, g = idx & 3;
            CP16(st + XBHI + sw64(r * 64 + g * 16),
                 wh + (size_t)(n0 + r) * 1024 + kc * 64 + g * 16);
        }
        #pragma unroll
        for (int i = 0; i < 2; i++) {
            int idx = tid + 256 * i;
            int r = idx >> 2, g = idx & 3;
            CP16(st + XBLO + sw64(r * 64 + g * 16),
                 wl + (size_t)(n0 + r) * 1024 + kc * 64 + g * 16);
        }
    };

    issue(0, 0); CP_COMMIT();

    const int mrow = 32 * (wid >> 1);
    const int ncol = 64 * (wid & 1);
    const int mi  = lane >> 3;
    const int mr  = lane & 7;
    const int rr  = lane & 15;

    for (int kc = 0; kc < 16; kc++) {
        int s = kc & 1;
        if (kc + 1 < 16) { issue(kc + 1, s ^ 1); CP_COMMIT(); CP_WAIT1(); }
        else             { CP_WAIT0(); }
        __syncthreads();

        uint32_t st = smb + s * XSTG;
        #pragma unroll
        for (int ks = 0; ks < 2; ks++) {
            uint32_t ah[2][4], al[2][4];
            #pragma unroll
            for (int mf = 0; mf < 2; mf++) {
                int row = mrow + 16 * mf + ((mi & 1) << 3) + mr;
                uint32_t off = row * 64 + ks * 32 + ((mi >> 1) << 4);
                ldsm_x4(ah[mf], st + XAHI + sw64(off));
                ldsm_x4(al[mf], st + XALO + sw64(off));
            }
            #pragma unroll
            for (int nf = 0; nf < 8; nf++) {
                uint32_t bh[2], bl[2];
                int brow = ncol + 8 * nf + (rr & 7);
                uint32_t boff = brow * 64 + ks * 32 + ((rr >> 3) << 4);
                ldsm_x2(bh, st + XBHI + sw64(boff));
                ldsm_x2(bl, st + XBLO + sw64(boff));
                #pragma unroll
                for (int mf = 0; mf < 2; mf++) {
                    mma16816(acc[mf][nf], ah[mf], bh);
                    mma16816(acc[mf][nf], ah[mf], bl);
                    mma16816(acc[mf][nf], al[mf], bh);
                }
            }
        }
        __syncthreads();
    }

    #pragma unroll
    for (int nf = 0; nf < 8; nf++) {
        int colg = n0 + ncol + 8 * nf + 2 * (lane & 3);
        float2 bv = *(const float2*)(bias + colg);
        #pragma unroll
        for (int mf = 0; mf < 2; mf++) {
            int rowg = m0 + mrow + 16 * mf + (lane >> 2);
            float2 o0 = make_float2(acc[mf][nf][0] + bv.x, acc[mf][nf][1] + bv.y);
            float2 o1 = make_float2(acc[mf][nf][2] + bv.x, acc[mf][nf][3] + bv.y);
            *(float2*)(g_xz + (size_t)rowg * G_ + colg)       = o0;
            *(float2*)(g_xz + (size_t)(rowg + 8) * G_ + colg) = o1;
        }
    }
}

// ---------------------------------------------------------------------------
// Persistent LSTM scan. Grid = 128 blocks (1/SM), 128 threads.
// Block owns 32 z-cols (8 u x 4 gates). R slice (hi+lo, 128 KB) loaded into
// smem ONCE; c state lives in registers; only h streams from L2 per step.
// Cross-step sync: per-step flag array + acquire polling (grid barrier).
// SMEM: R hi 64K | R lo 64K | h stages 2 x (8K hi + 8K lo) = 160 KB dynamic.
// ---------------------------------------------------------------------------
#define PRHI  0
#define PRLO  65536
#define PHST  131072
#define PHSTG 16384
#define PSMEM 163840

__global__ __launch_bounds__(128) void lstm_scan(float* __restrict__ out)
{
    extern __shared__ __align__(1024) char sm[];
    uint32_t smb = smem_u32(sm);
    const int tid  = threadIdx.x;
    const int wid  = tid >> 5;
    const int lane = tid & 31;
    const int bid  = blockIdx.x;
    const int u0   = bid * 8;

    const char* rh = (const char*)g_Rt_hi;
    const char* rl = (const char*)g_Rt_lo;

    // ---- Load resident R slice: 16 chunks x (32 cols x 128B), hi+lo ----
    #pragma unroll 4
    for (int i = 0; i < 32; i++) {
        int idx = tid + 128 * i;               // 0..4095 granules
        int kc = idx >> 8;
        int j  = idx & 255;
        int c  = j >> 3, g = j & 7;
        int n  = ((c >> 3) << 10) + u0 + (c & 7);      // gate*1024 + u
        size_t src = (size_t)n * 2048 + kc * 128 + g * 16;
        uint32_t dst = kc * 4096 + sw128(c * 128 + g * 16);
        CP16(smb + PRHI + dst, rh + src);
        CP16(smb + PRLO + dst, rl + src);
    }
    CP_COMMIT(); CP_WAIT0();
    __syncthreads();

    // ---- Per-thread state mapping (same fragment layout as R7 epilogue) ----
    const int b0 = 16 * wid + (lane >> 2);
    const int uu = u0 + 2 * (lane & 3);
    const int mi = lane >> 3;
    const int mr = lane & 7;
    const int rr = lane & 15;
    float c_reg[4] = {0.f, 0.f, 0.f, 0.f};   // [half*2 + j]

    for (int t = 0; t < T_; t++) {
        const char* hh = (const char*)g_hhi[t & 1];
        const char* hl = (const char*)g_hlo[t & 1];

        // Prefetch xz slice for this step (independent of h)
        float2 xzr[2][4];
        #pragma unroll
        for (int half = 0; half < 2; half++) {
            size_t xb = ((size_t)(b0 + 8 * half) * T_ + t) * G_ + uu;
            #pragma unroll
            for (int f = 0; f < 4; f++)
                xzr[half][f] = __ldg((const float2*)(g_xz + xb + f * U_));
        }

        auto issue_h = [&](int kc, int s) {
            uint32_t st = smb + PHST + s * PHSTG;
            #pragma unroll
            for (int i = 0; i < 4; i++) {
                int idx = tid + 128 * i;
                int r = idx >> 3, g = idx & 7;
                uint32_t so = sw128(r * 128 + g * 16);
                size_t src = (size_t)r * 2048 + kc * 128 + g * 16;
                CP16(st + so, hh + src);
                CP16(st + 8192 + so, hl + src);
            }
        };

        float acc[4][4] = {};   // [gate][frag]
        issue_h(0, 0); CP_COMMIT();

        for (int kc = 0; kc < 16; kc++) {
            int s = kc & 1;
            if (kc + 1 < 16) { issue_h(kc + 1, s ^ 1); CP_COMMIT(); CP_WAIT1(); }
            else             { CP_WAIT0(); }
            __syncthreads();

            uint32_t hst = smb + PHST + s * PHSTG;
            uint32_t rbs = smb + kc * 4096;
            #pragma unroll
            for (int ks = 0; ks < 4; ks++) {
                uint32_t ah[4], al[4];
                int row = 16 * wid + ((mi & 1) << 3) + mr;
                uint32_t off = row * 128 + ks * 32 + ((mi >> 1) << 4);
                ldsm_x4(ah, hst + sw128(off));
                ldsm_x4(al, hst + 8192 + sw128(off));
                #pragma unroll
                for (int f = 0; f < 4; f++) {
                    uint32_t bh[2], bl[2];
                    int brow = 8 * f + (rr & 7);
                    uint32_t boff = brow * 128 + ks * 32 + ((rr >> 3) << 4);
                    ldsm_x2(bh, rbs + PRHI + sw128(boff));
                    ldsm_x2(bl, rbs + PRLO + sw128(boff));
                    mma16816(acc[f], ah, bh);
                    mma16816(acc[f], ah, bl);
                    mma16816(acc[f], al, bh);
                }
            }
            __syncthreads();
        }

        // ---- Gate fusion + state update (c in registers) ----
        __nv_bfloat16* nh_hi = g_hhi[(t + 1) & 1];
        __nv_bfloat16* nh_lo = g_hlo[(t + 1) & 1];
        #pragma unroll
        for (int half = 0; half < 2; half++) {
            int b = b0 + 8 * half;
            float hv[2];
            #pragma unroll
            for (int j = 0; j < 2; j++) {
                int a = 2 * half + j;
                float zi = acc[0][a] + (j ? xzr[half][0].y : xzr[half][0].x);
                float zf = acc[1][a] + (j ? xzr[half][1].y : xzr[half][1].x);
                float zc = acc[2][a] + (j ? xzr[half][2].y : xzr[half][2].x);
                float zo = acc[3][a] + (j ? xzr[half][3].y : xzr[half][3].x);
                float ig = 1.0f / (1.0f + __expf(-zi));
                float fg = 1.0f / (1.0f + __expf(-zf));
                float og = 1.0f / (1.0f + __expf(-zo));
                float cn = fg * c_reg[a] + ig * tanhf(zc);
                c_reg[a] = cn;
                hv[j] = og * tanhf(cn);
            }
            if (t == T_ - 1) {
                *(float2*)(out + b * U_ + uu) = make_float2(hv[0], hv[1]);
            } else {
                __nv_bfloat16 h0 = __float2bfloat16(hv[0]);
                __nv_bfloat16 h1 = __float2bfloat16(hv[1]);
                *(__nv_bfloat162*)(nh_hi + b * U_ + uu) = __halves2bfloat162(h0, h1);
                *(__nv_bfloat162*)(nh_lo + b * U_ + uu) = __halves2bfloat162(
                    __float2bfloat16(hv[0] - __bfloat162float(h0)),
                    __float2bfloat16(hv[1] - __bfloat162float(h1)));
            }
        }

        // ---- Grid barrier: publish our h slice, wait for all 128 blocks ----
        if (t < T_ - 1) {
            __syncthreads();                     // all h writes of this block done
            if (tid == 0) {
                __threadfence();                 // make them visible gpu-wide
                asm volatile("st.release.gpu.global.u32 [%0], %1;"
                             :: "l"(g_flags + t * 128 + bid), "r"(1) : "memory");
            }
            if (tid < 32) {
                const int* fl = g_flags + t * 128 + lane * 4;
                uint4 v;
                while (true) {
                    asm volatile("ld.acquire.gpu.global.v4.u32 {%0,%1,%2,%3}, [%4];"
                                 : "=r"(v.x), "=r"(v.y), "=r"(v.z), "=r"(v.w)
                                 : "l"(fl));
                    if (v.x & v.y & v.z & v.w) break;
                    __nanosleep(60);
                }
            }
            __syncthreads();                     // barrier result visible block-wide
        }
    }
}

// ---------------------------------------------------------------------------
extern "C" void kernel_launch(void* const* d_in, const int* in_sizes, int n_in,
                              void* d_out, int out_size)
{
    const float* x    = (const float*)d_in[0];   // [64, 512, 512]
    const float* W    = (const float*)d_in[1];   // [512, 4096]
    const float* R    = (const float*)d_in[2];   // [1024, 4096]
    const float* bias = (const float*)d_in[3];   // [4096]
    float* out = (float*)d_out;                  // [64, 1024]

    cudaFuncSetAttribute(gemm_xz_mma,
                         cudaFuncAttributeMaxDynamicSharedMemorySize, 2 * XSTG);
    cudaFuncSetAttribute(lstm_scan,
                         cudaFuncAttributeMaxDynamicSharedMemorySize, PSMEM);

    init_state<<<256, 256>>>();
    split_x<<<(B_ * T_ * D_ / 4 + 255) / 256, 256>>>(x);
    transpose_split_sel<<<dim3(G_ / 32, D_ / 32), dim3(32, 8)>>>(W, 0, D_, G_);
    transpose_split_sel<<<dim3(G_ / 32, U_ / 32), dim3(32, 8)>>>(R, 1, U_, G_);
    gemm_xz_mma<<<dim3(G_ / 128, (B_ * T_) / 128), 256, 2 * XSTG>>>(bias);
    lstm_scan<<<128, 128, PSMEM>>>(out);
}